// round 8
// baseline (speedup 1.0000x reference)
#include <cuda_runtime.h>

#define VOCAB  200000
#define DIM    128
#define NPOS   10
#define NNEG   64
#define NCTX   (NPOS + NNEG)       // 74
#define NROWS  (1 + NPOS + NNEG)   // 75
#define VEC_PER_ROW (VOCAB / 4)    // 50000 float4 per row

#define THREADS 256
#define LOADS   8
#define COVER   (THREADS * LOADS)  // 2048 float4 per block

#define CENTER_VEC (VEC_PER_ROW)            // 12500
#define POS_VEC    (NPOS * VEC_PER_ROW)     // 500000
#define NEG_VEC    (NNEG * VEC_PER_ROW)     // 3200000
#define CB ((CENTER_VEC + COVER - 1) / COVER)   // 7
#define PB ((POS_VEC    + COVER - 1) / COVER)   // 245
#define NB ((NEG_VEC    + COVER - 1) / COVER)   // 1563
#define GRID_A (CB + PB + NB)                   // 1815

// Scratch (alloc-free rule: __device__ globals).
__device__ float g_vec[NROWS][DIM];   // staged embedding vectors (38.4 KB)

// Numerically stable log_sigmoid(x) = -softplus(-x)
__device__ __forceinline__ float log_sigmoidf(float x) {
    return (x >= 0.0f) ? -log1pf(expf(-x)) : (x - log1pf(expf(x)));
}

// Rare path: on one-hot hit, gather this word's embedding vector into the
// staging buffer. Runs on <=75 threads grid-wide, overlapped with streaming.
__device__ __forceinline__ void hit_test(float4 v4, int i, int row_base,
                                         const float* __restrict__ inE,
                                         const float* __restrict__ outE) {
    uint4 u = *reinterpret_cast<uint4*>(&v4);   // one-hot: bitwise test safe
    if ((u.x | u.y | u.z | u.w) != 0u) {
        int row  = i / VEC_PER_ROW;             // const-div -> mul
        int vv   = i - row * VEC_PER_ROW;
        int sub  = (u.x != 0u) ? 0 : (u.y != 0u) ? 1 : (u.z != 0u) ? 2 : 3;
        int gr   = row_base + row;              // 0..74
        int word = 4 * vv + sub;                // vocab index
        if (gr <= NPOS) {
            // center / positive: column of inE (stride VOCAB)
            #pragma unroll
            for (int d = 0; d < DIM; d++)
                g_vec[gr][d] = __ldg(&inE[(long)d * VOCAB + word]);
        } else {
            // negative: contiguous row of outE
            const float4* r = (const float4*)(outE + (long)word * DIM);
            #pragma unroll
            for (int j = 0; j < DIM / 4; j++)
                ((float4*)g_vec[gr])[j] = __ldg(&r[j]);
        }
    }
}

// ---------------------------------------------------------------------------
// Kernel A: stream 60 MB of one-hot data (structural MLP=8 batched __ldcs),
// stage embedding vectors on hit. Block 0 zero-inits the output scalar.
// ---------------------------------------------------------------------------
__global__ void skipgram_find_idx(const float4* __restrict__ center,
                                  const float4* __restrict__ pos,
                                  const float4* __restrict__ neg,
                                  const float*  __restrict__ inE,
                                  const float*  __restrict__ outE,
                                  float* __restrict__ out) {
    const int tid = threadIdx.x;
    const int b   = blockIdx.x;
    if (b == 0 && tid == 0) *out = 0.0f;

    const float4* base;
    int nvec, row_base, lb;
    if (b < CB)           { base = center; nvec = CENTER_VEC; row_base = 0;        lb = b; }
    else if (b < CB + PB) { base = pos;    nvec = POS_VEC;    row_base = 1;        lb = b - CB; }
    else                  { base = neg;    nvec = NEG_VEC;    row_base = 1 + NPOS; lb = b - CB - PB; }

    const int seg = lb * COVER;
    const int off = seg + tid;

    if (seg + COVER <= nvec) {
        // fast path: branch-free batched loads (MLP=8)
        float4 x[LOADS];
        #pragma unroll
        for (int k = 0; k < LOADS; k++)
            x[k] = __ldcs(base + off + k * THREADS);
        #pragma unroll
        for (int k = 0; k < LOADS; k++)
            hit_test(x[k], off + k * THREADS, row_base, inE, outE);
    } else {
        // boundary block: checked loads
        #pragma unroll
        for (int k = 0; k < LOADS; k++) {
            int i = off + k * THREADS;
            if (i < nvec) hit_test(__ldcs(base + i), i, row_base, inE, outE);
        }
    }
}

// ---------------------------------------------------------------------------
// Kernel B: 74 blocks x 128 threads; reads only the staged (L2-hot) vectors.
// One memory round -> dot -> log_sigmoid -> atomicAdd.
// ---------------------------------------------------------------------------
__global__ void skipgram_score(float* __restrict__ out) {
    __shared__ float partial[4];

    const int w    = blockIdx.x;          // 0..73
    const int d    = threadIdx.x;         // 0..127
    const int wid  = d >> 5;
    const int lane = d & 31;

    const float vd = g_vec[0][d];
    const float ud = g_vec[1 + w][d];

    float dot = vd * ud;
    #pragma unroll
    for (int s = 16; s; s >>= 1) dot += __shfl_xor_sync(0xFFFFFFFFu, dot, s);
    if (lane == 0) partial[wid] = dot;
    __syncthreads();

    if (d == 0) {
        float t = partial[0] + partial[1] + partial[2] + partial[3];
        float x = (w < NPOS) ? t : -t;
        atomicAdd(out, -log_sigmoidf(x));
    }
}

extern "C" void kernel_launch(void* const* d_in, const int* in_sizes, int n_in,
                              void* d_out, int out_size) {
    const float* center = (const float*)d_in[0];   // [VOCAB]
    const float* pos    = (const float*)d_in[1];   // [NPOS, VOCAB]
    const float* neg    = (const float*)d_in[2];   // [NNEG, VOCAB]
    const float* inE    = (const float*)d_in[3];   // [DIM, VOCAB]
    const float* outE   = (const float*)d_in[4];   // [VOCAB, DIM]
    float* out = (float*)d_out;

    skipgram_find_idx<<<GRID_A, THREADS>>>((const float4*)center,
                                           (const float4*)pos,
                                           (const float4*)neg,
                                           inE, outE, out);
    skipgram_score<<<NCTX, DIM>>>(out);
}